// round 14
// baseline (speedup 1.0000x reference)
#include <cuda_runtime.h>
#include <math.h>
#include <stdint.h>

#define FLTMAX 3.402823466e38f

// ---------------- static device scratch ----------------
__device__ float g_emb[(size_t)32768 * 33];     // [b*512+s][33]
__device__ float g_xw [(size_t)32768 * 1536];   // [b*512+t][1536]
__device__ float g_h  [(size_t)32768 * 512];    // [b*512+t][512]
__device__ float g_valid[32768];                // final-order validity (0/1)
__device__ int   g_bar[8];                      // group barriers (layer0: 0..3, layer1: 4..7)

// ---------------- f32x2 packed math (sm_100+) ----------------
#define PACK2(d, s)  asm("mov.b64 %0, {%1, %1};" : "=l"(d) : "r"(__float_as_uint(s)))
#define UNPACK2(lo, hi, v) asm("mov.b64 {%0, %1}, %2;" : "=f"(lo), "=f"(hi) : "l"(v))
#define FMA2(a, x, y) asm("fma.rn.f32x2 %0, %1, %2, %0;" : "+l"(a) : "l"(x), "l"(y))

// ---------------- helpers ----------------
__device__ __forceinline__ unsigned f2o(float x) {
    unsigned u = __float_as_uint(x);
    return (u & 0x80000000u) ? ~u : (u | 0x80000000u);
}

// 512-element ascending bitonic sort, 256 threads, 64-bit keys in smem
__device__ void bitonic512(unsigned long long* key, int tid) {
    for (int k = 2; k <= 512; k <<= 1) {
        for (int j = k >> 1; j > 0; j >>= 1) {
            __syncthreads();
            int low = tid & (j - 1);
            int i   = ((tid & ~(j - 1)) << 1) | low;
            int i2  = i | j;
            bool up = ((i & k) == 0);
            unsigned long long a = key[i], c = key[i2];
            if ((a > c) == up) { key[i] = c; key[i2] = a; }
        }
    }
    __syncthreads();
}

__global__ void zero_bar_kernel() {
    if (threadIdx.x < 8) g_bar[threadIdx.x] = 0;
}

// ---------------- 1. preprocess (verified: rel_err 5.9e-7) ----------------
__global__ void __launch_bounds__(256) prep_kernel(const float* __restrict__ lc,
                                                   const float* __restrict__ freq) {
    int b = blockIdx.x, tid = threadIdx.x;
    __shared__ float ph[512], mg[512], sps[512], sms[512], oph[512];
    __shared__ int   oval[512];
    __shared__ unsigned long long key[512];
    __shared__ float smoothv[52];
    __shared__ float s_shift;

    float period = 2.0f / freq[b];
    for (int s = tid; s < 512; s += 256) {
        float tm = lc[b * 1536 + s];
        float m  = lc[b * 1536 + 512 + s];
        float p  = fmodf(tm, period) / period;
        ph[s] = p; mg[s] = m;
        key[s] = ((unsigned long long)f2o(p) << 32) | (unsigned)s;
    }
    bitonic512(key, tid);

    for (int i = tid; i < 512; i += 256) {
        int p = (int)(key[i] & 0xffffffffu);
        sps[i] = ph[p]; sms[i] = mg[p];
    }
    __syncthreads();

    for (int i = tid; i < 512; i += 256) {
        float p0 = sps[i];
        const int offs[4] = {-2, -1, 1, 2};
        float wv[4], mv[4];
        float wsum = 0.f, wm = 0.f;
#pragma unroll
        for (int d = 0; d < 4; ++d) {
            int j = (i + offs[d] + 512) & 511;
            float dp = sps[j] - p0 - 0.5f;
            dp = dp - floorf(dp) - 0.5f;
            float w = 0.75f * (1.0f - dp * dp);
            wv[d] = w; mv[d] = sms[j];
            wsum += w; wm += w * mv[d];
        }
        float loc = wm / wsum;
        float var = 0.f;
#pragma unroll
        for (int d = 0; d < 4; ++d) { float e = mv[d] - loc; var += e * e * wv[d]; }
        float scale = sqrtf(var / (wsum - 1.0f));
        float thr = loc + 5.0f * scale;
        int valid = !(sms[i] > thr);
        int p = (int)(key[i] & 0xffffffffu);
        oval[p] = valid;
    }
    __syncthreads();

    int warp = tid >> 5, lane = tid & 31;
    for (int g = warp; g < 50; g += 8) {
        float gv = (float)g * (1.0f / 49.0f);
        float num = 0.f, den = 0.f;
        for (int s = lane; s < 512; s += 32) {
            if (oval[s]) {
                float d = gv - ph[s];
                float K = expf((cosf(6.2831855f * d) - 1.0f) / 0.01f);
                num += K * mg[s]; den += K;
            }
        }
#pragma unroll
        for (int o = 16; o > 0; o >>= 1) {
            num += __shfl_down_sync(0xffffffffu, num, o);
            den += __shfl_down_sync(0xffffffffu, den, o);
        }
        if (lane == 0) smoothv[g] = num / den;
    }
    __syncthreads();
    if (tid == 0) {
        float best = smoothv[0]; int bi = 0;
        for (int g = 1; g < 50; ++g)
            if (smoothv[g] > best) { best = smoothv[g]; bi = g; }
        s_shift = (float)bi * (1.0f / 49.0f);
    }
    __syncthreads();

    float shift = s_shift;
    for (int s = tid; s < 512; s += 256) {
        float p2 = ph[s] - shift;
        oph[s] = p2;
        float kv = oval[s] ? p2 : FLTMAX;
        key[s] = ((unsigned long long)f2o(kv) << 32) | (unsigned)s;
    }
    bitonic512(key, tid);

    for (int i = tid; i < 512; i += 256) {
        int s = (int)(key[i] & 0xffffffffu);
        float p = oph[s], m = mg[s];
        size_t row = ((size_t)b * 512 + i) * 33;
        float base = 6.2831855f * p;
#pragma unroll
        for (int h = 0; h < 16; ++h) {
            float sv, cv;
            sincosf(base * (float)(h + 1), &sv, &cv);
            g_emb[row + h]      = cv;
            g_emb[row + 16 + h] = sv;
        }
        g_emb[row + 32] = m;
        g_valid[b * 512 + i] = (float)oval[s];
    }
}

// ---------------- 2a. scalar GEMM (K=33): C = A.B^T + bias ----------------
__global__ void __launch_bounds__(256) gemm_tn(const float* __restrict__ A,
                                               const float* __restrict__ B,
                                               const float* __restrict__ bias,
                                               float* __restrict__ C,
                                               int M, int N, int K) {
    __shared__ float As[8][132], Bs[8][132];
    int bm = blockIdx.y * 128, bn = blockIdx.x * 128;
    int tid = threadIdx.x, tm = tid >> 4, tn = tid & 15;
    float acc[8][8];
#pragma unroll
    for (int i = 0; i < 8; ++i)
#pragma unroll
        for (int j = 0; j < 8; ++j) acc[i][j] = 0.f;

    for (int k0 = 0; k0 < K; k0 += 8) {
#pragma unroll
        for (int i = 0; i < 4; ++i) {
            int idx = tid + i * 256;
            int r = idx >> 3, kk = idx & 7;
            As[kk][r] = (k0 + kk < K) ? A[(size_t)(bm + r) * K + k0 + kk] : 0.f;
            Bs[kk][r] = (k0 + kk < K) ? B[(size_t)(bn + r) * K + k0 + kk] : 0.f;
        }
        __syncthreads();
#pragma unroll
        for (int kk = 0; kk < 8; ++kk) {
            float a[8], bb[8];
#pragma unroll
            for (int i = 0; i < 8; ++i) a[i]  = As[kk][tm * 8 + i];
#pragma unroll
            for (int j = 0; j < 8; ++j) bb[j] = Bs[kk][tn * 8 + j];
#pragma unroll
            for (int i = 0; i < 8; ++i)
#pragma unroll
                for (int j = 0; j < 8; ++j) acc[i][j] += a[i] * bb[j];
        }
        __syncthreads();
    }
#pragma unroll
    for (int i = 0; i < 8; ++i)
#pragma unroll
        for (int j = 0; j < 8; ++j)
            C[(size_t)(bm + tm * 8 + i) * N + bn + tn * 8 + j] = acc[i][j] + bias[bn + tn * 8 + j];
}

// ---------------- 2b. packed-f32x2 GEMM (K multiple of 8) ----------------
__global__ void __launch_bounds__(256) gemm_tn_x2(const float* __restrict__ A,
                                                  const float* __restrict__ B,
                                                  const float* __restrict__ bias,
                                                  float* __restrict__ C,
                                                  int M, int N, int K) {
    __shared__ float As[8][132], Bs[8][132];
    int bm = blockIdx.y * 128, bn = blockIdx.x * 128;
    int tid = threadIdx.x, tm = tid >> 4, tn = tid & 15;
    unsigned long long acc[8][4];
#pragma unroll
    for (int i = 0; i < 8; ++i)
#pragma unroll
        for (int j = 0; j < 4; ++j) acc[i][j] = 0ull;

    for (int k0 = 0; k0 < K; k0 += 8) {
#pragma unroll
        for (int i = 0; i < 4; ++i) {
            int idx = tid + i * 256;
            int r = idx >> 3, kk = idx & 7;
            As[kk][r] = A[(size_t)(bm + r) * K + k0 + kk];
            Bs[kk][r] = B[(size_t)(bn + r) * K + k0 + kk];
        }
        __syncthreads();
#pragma unroll
        for (int kk = 0; kk < 8; ++kk) {
            float4 alo = *(const float4*)&As[kk][tm * 8];
            float4 ahi = *(const float4*)&As[kk][tm * 8 + 4];
            unsigned long long a2[8];
            PACK2(a2[0], alo.x); PACK2(a2[1], alo.y); PACK2(a2[2], alo.z); PACK2(a2[3], alo.w);
            PACK2(a2[4], ahi.x); PACK2(a2[5], ahi.y); PACK2(a2[6], ahi.z); PACK2(a2[7], ahi.w);
            unsigned long long b2[4];
#pragma unroll
            for (int jj = 0; jj < 4; ++jj)
                b2[jj] = *(const unsigned long long*)&Bs[kk][tn * 8 + jj * 2];
#pragma unroll
            for (int i = 0; i < 8; ++i)
#pragma unroll
                for (int jj = 0; jj < 4; ++jj)
                    FMA2(acc[i][jj], a2[i], b2[jj]);
        }
        __syncthreads();
    }
#pragma unroll
    for (int i = 0; i < 8; ++i) {
        size_t row = (size_t)(bm + tm * 8 + i);
#pragma unroll
        for (int jj = 0; jj < 4; ++jj) {
            int col = bn + tn * 8 + jj * 2;
            float lo, hi;
            UNPACK2(lo, hi, acc[i][jj]);
            float2 v = make_float2(lo + bias[col], hi + bias[col + 1]);
            *(float2*)&C[row * N + col] = v;
        }
    }
}

// ---------------- 3. persistent GRU layer (K-packed f32x2: zero packing MOVs) ----------------
// grid = 128: group g = blockIdx/32 owns batches [16g,16g+16); chunk c = blockIdx%32 owns h-cols [16c,16c+16)
// Dot: thread = jig(8) x bq(4), ks = warp (0..7, k-chunk 64); thread owns 6 gate-rows x 4 batches (b = 4o+bq).
// f32x2 lanes pack (k, k+1): W and h consumed directly as ulonglong2 smem loads, no PACK2.
// smem: W 48x516 f | h 16x520 f (plain k-major) | partials 768 segs x 9 f | bhh 48 f
#define HROW 520
#define GRU_SMEM_BYTES ((48*516 + 16*HROW + 768*9 + 48)*4)
__global__ void __launch_bounds__(256, 1) gru_kernel(const float* __restrict__ xw,
                                                     const float* __restrict__ whh,
                                                     const float* __restrict__ bhh,
                                                     float* __restrict__ hout,
                                                     int* __restrict__ bar) {
    int c = blockIdx.x & 31;
    int grp = blockIdx.x >> 5;
    int b0 = grp * 16;
    int tid = threadIdx.x;

    extern __shared__ float sm[];
    float* sW   = sm;                    // 48 x 516
    float* sh   = sW + 48 * 516;         // 16 x 520 (batch-major, plain k layout)
    float* sp   = sh + 16 * HROW;        // 768 segments x 9 floats
    float* sbhh = sp + 768 * 9;          // 48

    // load W_hh slice: smem row r = g*16+j <- global row g*512 + c*16 + j
    for (int idx = tid; idx < 48 * 512; idx += 256) {
        int r = idx >> 9, k = idx & 511;
        int grow = (r >> 4) * 512 + c * 16 + (r & 15);
        sW[r * 516 + k] = whh[(size_t)grow * 512 + k];
    }
    if (tid < 48) sbhh[tid] = bhh[(tid >> 4) * 512 + c * 16 + (tid & 15)];
    for (int idx = tid; idx < 16 * HROW; idx += 256) sh[idx] = 0.f;  // h0 = 0
    __syncthreads();

    // dot-phase mapping: jig = tid&7 (cols jig, jig+8), bq = (tid>>3)&3, ks = tid>>5 (k-chunk 64)
    int jig = tid & 7;
    int bq  = (tid >> 3) & 3;
    int ks  = tid >> 5;

    const float* Wp[6];
#pragma unroll
    for (int g = 0; g < 3; ++g)
#pragma unroll
        for (int hf = 0; hf < 2; ++hf)
            Wp[g * 2 + hf] = sW + (g * 16 + jig + hf * 8) * 516 + ks * 64;
    const float* hbase = sh + bq * HROW + ks * 64;   // batch b = 4o+bq at +o*4*HROW

    // combine mapping (all 256 threads): batch b16 = tid>>4, column cj = tid&15
    int b16 = tid >> 4, cj = tid & 15;
    const float* xbase = xw + ((size_t)(b0 + b16) * 512) * 1536 + c * 16 + cj;

    int target = 0;
    for (int t = 0; t < 512; ++t) {
        // prefetch xW for combine (consumed ~3000 cycles later)
        const float* x0 = xbase + (size_t)t * 1536;
        float xr = x0[0], xz = x0[512], xn = x0[1024];

        unsigned long long acc[6][4];
#pragma unroll
        for (int a = 0; a < 6; ++a)
#pragma unroll
            for (int o = 0; o < 4; ++o) acc[a][o] = 0ull;

#pragma unroll
        for (int i = 0; i < 16; ++i) {
            ulonglong2 wv[6];
#pragma unroll
            for (int a = 0; a < 6; ++a)
                wv[a] = *(const ulonglong2*)(Wp[a] + i * 4);
#pragma unroll
            for (int o = 0; o < 4; ++o) {
                ulonglong2 hv = *(const ulonglong2*)(hbase + o * (4 * HROW) + i * 4);
#pragma unroll
                for (int a = 0; a < 6; ++a) {
                    FMA2(acc[a][o], wv[a].x, hv.x);
                    FMA2(acc[a][o], wv[a].y, hv.y);
                }
            }
        }

        // lane-sum (even-k + odd-k) and write scalar partials: sp[((b*16+col)*3+g)*9 + ks]
#pragma unroll
        for (int a = 0; a < 6; ++a) {
            int g = a >> 1, col = jig + (a & 1) * 8;
#pragma unroll
            for (int o = 0; o < 4; ++o) {
                int b = 4 * o + bq;
                float lo, hi;
                UNPACK2(lo, hi, acc[a][o]);
                sp[((b * 16 + col) * 3 + g) * 9 + ks] = lo + hi;
            }
        }
        __syncthreads();

        // combine + activation (256 threads: one (batch, col) element each; conflict-free loads)
        {
            float s[3];
#pragma unroll
            for (int g = 0; g < 3; ++g) {
                int base = (tid * 3 + g) * 9;   // tid = b16*16+cj
                float a2 = 0.f;
#pragma unroll
                for (int q = 0; q < 8; ++q) a2 += sp[base + q];
                s[g] = a2;
            }
            float hprev = sh[b16 * HROW + c * 16 + cj];

            float r = 1.f / (1.f + expf(-(xr + s[0] + sbhh[cj])));
            float z = 1.f / (1.f + expf(-(xz + s[1] + sbhh[16 + cj])));
            float n = tanhf(xn + r * (s[2] + sbhh[32 + cj]));
            float hnew = (1.f - z) * n + z * hprev;

            hout[((size_t)(b0 + b16) * 512 + t) * 512 + c * 16 + cj] = hnew;
        }
        __syncthreads();

        // group barrier (monotonic counter, release/acquire through L2) — champion verbatim
        if (tid == 0) {
            __threadfence();
            atomicAdd(&bar[grp], 1);
            target += 32;
            volatile int* vb = (volatile int*)(bar + grp);
            while (*vb < target) __nanosleep(32);
        }
        __syncthreads();

        // reload full h_t (plain layout: straight float4 copy; fresh addresses each t)
#pragma unroll
        for (int it = 0; it < 8; ++it) {
            int idx = tid + it * 256;
            int p = idx >> 7, kq = idx & 127;
            float4 v = *(const float4*)&hout[((size_t)(b0 + p) * 512 + t) * 512 + kq * 4];
            *(float4*)&sh[p * HROW + kq * 4] = v;
        }
        __syncthreads();
    }
}

// ---------------- 4. masked mean + MLP head ----------------
__global__ void __launch_bounds__(256) final_kernel(const float* __restrict__ Wl1,
                                                    const float* __restrict__ bl1,
                                                    const float* __restrict__ Wl2,
                                                    const float* __restrict__ bl2,
                                                    float* __restrict__ out) {
    int b = blockIdx.x, tid = threadIdx.x;
    __shared__ float sval[512], ctx[512], h1[512], red[8];
    __shared__ float s_cnt;
    int warp = tid >> 5, lane = tid & 31;

    for (int s = tid; s < 512; s += 256) sval[s] = g_valid[b * 512 + s];
    __syncthreads();

    float cp = sval[tid] + sval[tid + 256];
#pragma unroll
    for (int o = 16; o > 0; o >>= 1) cp += __shfl_down_sync(0xffffffffu, cp, o);
    if (lane == 0) red[warp] = cp;
    __syncthreads();
    if (tid == 0) {
        float cnt = 0.f;
        for (int w = 0; w < 8; ++w) cnt += red[w];
        s_cnt = cnt;
    }
    __syncthreads();

#pragma unroll
    for (int cc = 0; cc < 2; ++cc) {
        int col = tid + cc * 256;
        float acc = 0.f;
        for (int t = 0; t < 512; ++t)
            acc += g_h[((size_t)b * 512 + t) * 512 + col] * sval[t];
        ctx[col] = acc / s_cnt;
    }
    __syncthreads();

#pragma unroll
    for (int cc = 0; cc < 2; ++cc) {
        int o = tid + cc * 256;
        float a = 0.f;
        const float* wr = Wl1 + (size_t)o * 512;
        for (int k = 0; k < 512; ++k) a += ctx[k] * wr[k];
        a += bl1[o];
        h1[o] = 0.5f * a * (1.0f + erff(a * 0.70710678118654752f));
    }
    __syncthreads();

    for (int o = warp; o < 16; o += 8) {
        float a = 0.f;
        const float* wr = Wl2 + (size_t)o * 512;
        for (int k = lane; k < 512; k += 32) a += h1[k] * wr[k];
#pragma unroll
        for (int s = 16; s > 0; s >>= 1) a += __shfl_down_sync(0xffffffffu, a, s);
        if (lane == 0) out[b * 16 + o] = a + bl2[o];
    }
}

// ---------------- launch ----------------
extern "C" void kernel_launch(void* const* d_in, const int* in_sizes, int n_in,
                              void* d_out, int out_size) {
    const float* lc    = (const float*)d_in[0];
    const float* freq  = (const float*)d_in[2];
    const float* W_ih0 = (const float*)d_in[3];
    const float* b_ih0 = (const float*)d_in[4];
    const float* W_hh0 = (const float*)d_in[5];
    const float* b_hh0 = (const float*)d_in[6];
    const float* W_ih1 = (const float*)d_in[7];
    const float* b_ih1 = (const float*)d_in[8];
    const float* W_hh1 = (const float*)d_in[9];
    const float* b_hh1 = (const float*)d_in[10];
    const float* Wl1   = (const float*)d_in[11];
    const float* bl1   = (const float*)d_in[12];
    const float* Wl2   = (const float*)d_in[13];
    const float* bl2   = (const float*)d_in[14];
    float* out = (float*)d_out;

    float *p_emb, *p_xw, *p_h;
    int* p_bar;
    cudaGetSymbolAddress((void**)&p_emb, g_emb);
    cudaGetSymbolAddress((void**)&p_xw,  g_xw);
    cudaGetSymbolAddress((void**)&p_h,   g_h);
    cudaGetSymbolAddress((void**)&p_bar, g_bar);

    cudaFuncSetAttribute(gru_kernel, cudaFuncAttributeMaxDynamicSharedMemorySize, GRU_SMEM_BYTES);

    zero_bar_kernel<<<1, 32>>>();
    prep_kernel<<<64, 256>>>(lc, freq);

    // xW0 = emb @ W_ih0^T + b_ih0   (M=32768, N=1536, K=33) — scalar (K odd)
    gemm_tn<<<dim3(12, 256), 256>>>(p_emb, W_ih0, b_ih0, p_xw, 32768, 1536, 33);

    // GRU layer 0
    gru_kernel<<<128, 256, GRU_SMEM_BYTES>>>(p_xw, W_hh0, b_hh0, p_h, p_bar);

    // xW1 = hs0 @ W_ih1^T + b_ih1   (K=512) — packed f32x2
    gemm_tn_x2<<<dim3(12, 256), 256>>>(p_h, W_ih1, b_ih1, p_xw, 32768, 1536, 512);

    // GRU layer 1 (separate barrier counters; hs1 overwrites g_h)
    gru_kernel<<<128, 256, GRU_SMEM_BYTES>>>(p_xw, W_hh1, b_hh1, p_h, p_bar + 4);

    final_kernel<<<64, 256>>>(Wl1, bl1, Wl2, bl2, out);
}

// round 16
// speedup vs baseline: 1.0578x; 1.0578x over previous
#include <cuda_runtime.h>
#include <math.h>
#include <stdint.h>

#define FLTMAX 3.402823466e38f

// ---------------- static device scratch ----------------
__device__ float g_emb[(size_t)32768 * 33];     // [b*512+s][33]
__device__ float g_xw [(size_t)32768 * 1536];   // [b*512+t][1536]
__device__ float g_h  [(size_t)32768 * 512];    // [b*512+t][512]
__device__ float g_valid[32768];                // final-order validity (0/1)
// one barrier counter per 128-byte L2 line: group g of layer l at index (l*4+g)*32
__device__ int   g_bar[8 * 32];

// ---------------- f32x2 packed math (sm_100+) ----------------
#define PACK2(d, s)  asm("mov.b64 %0, {%1, %1};" : "=l"(d) : "r"(__float_as_uint(s)))
#define UNPACK2(lo, hi, v) asm("mov.b64 {%0, %1}, %2;" : "=f"(lo), "=f"(hi) : "l"(v))
#define FMA2(a, x, y) asm("fma.rn.f32x2 %0, %1, %2, %0;" : "+l"(a) : "l"(x), "l"(y))

// ---------------- helpers ----------------
__device__ __forceinline__ unsigned f2o(float x) {
    unsigned u = __float_as_uint(x);
    return (u & 0x80000000u) ? ~u : (u | 0x80000000u);
}

// 512-element ascending bitonic sort, 256 threads, 64-bit keys in smem
__device__ void bitonic512(unsigned long long* key, int tid) {
    for (int k = 2; k <= 512; k <<= 1) {
        for (int j = k >> 1; j > 0; j >>= 1) {
            __syncthreads();
            int low = tid & (j - 1);
            int i   = ((tid & ~(j - 1)) << 1) | low;
            int i2  = i | j;
            bool up = ((i & k) == 0);
            unsigned long long a = key[i], c = key[i2];
            if ((a > c) == up) { key[i] = c; key[i2] = a; }
        }
    }
    __syncthreads();
}

__global__ void zero_bar_kernel() {
    if (threadIdx.x < 8 * 32) g_bar[threadIdx.x] = 0;
}

// ---------------- 1. preprocess (verified: rel_err 5.9e-7) ----------------
__global__ void __launch_bounds__(256) prep_kernel(const float* __restrict__ lc,
                                                   const float* __restrict__ freq) {
    int b = blockIdx.x, tid = threadIdx.x;
    __shared__ float ph[512], mg[512], sps[512], sms[512], oph[512];
    __shared__ int   oval[512];
    __shared__ unsigned long long key[512];
    __shared__ float smoothv[52];
    __shared__ float s_shift;

    float period = 2.0f / freq[b];
    for (int s = tid; s < 512; s += 256) {
        float tm = lc[b * 1536 + s];
        float m  = lc[b * 1536 + 512 + s];
        float p  = fmodf(tm, period) / period;
        ph[s] = p; mg[s] = m;
        key[s] = ((unsigned long long)f2o(p) << 32) | (unsigned)s;
    }
    bitonic512(key, tid);

    for (int i = tid; i < 512; i += 256) {
        int p = (int)(key[i] & 0xffffffffu);
        sps[i] = ph[p]; sms[i] = mg[p];
    }
    __syncthreads();

    for (int i = tid; i < 512; i += 256) {
        float p0 = sps[i];
        const int offs[4] = {-2, -1, 1, 2};
        float wv[4], mv[4];
        float wsum = 0.f, wm = 0.f;
#pragma unroll
        for (int d = 0; d < 4; ++d) {
            int j = (i + offs[d] + 512) & 511;
            float dp = sps[j] - p0 - 0.5f;
            dp = dp - floorf(dp) - 0.5f;
            float w = 0.75f * (1.0f - dp * dp);
            wv[d] = w; mv[d] = sms[j];
            wsum += w; wm += w * mv[d];
        }
        float loc = wm / wsum;
        float var = 0.f;
#pragma unroll
        for (int d = 0; d < 4; ++d) { float e = mv[d] - loc; var += e * e * wv[d]; }
        float scale = sqrtf(var / (wsum - 1.0f));
        float thr = loc + 5.0f * scale;
        int valid = !(sms[i] > thr);
        int p = (int)(key[i] & 0xffffffffu);
        oval[p] = valid;
    }
    __syncthreads();

    int warp = tid >> 5, lane = tid & 31;
    for (int g = warp; g < 50; g += 8) {
        float gv = (float)g * (1.0f / 49.0f);
        float num = 0.f, den = 0.f;
        for (int s = lane; s < 512; s += 32) {
            if (oval[s]) {
                float d = gv - ph[s];
                float K = expf((cosf(6.2831855f * d) - 1.0f) / 0.01f);
                num += K * mg[s]; den += K;
            }
        }
#pragma unroll
        for (int o = 16; o > 0; o >>= 1) {
            num += __shfl_down_sync(0xffffffffu, num, o);
            den += __shfl_down_sync(0xffffffffu, den, o);
        }
        if (lane == 0) smoothv[g] = num / den;
    }
    __syncthreads();
    if (tid == 0) {
        float best = smoothv[0]; int bi = 0;
        for (int g = 1; g < 50; ++g)
            if (smoothv[g] > best) { best = smoothv[g]; bi = g; }
        s_shift = (float)bi * (1.0f / 49.0f);
    }
    __syncthreads();

    float shift = s_shift;
    for (int s = tid; s < 512; s += 256) {
        float p2 = ph[s] - shift;
        oph[s] = p2;
        float kv = oval[s] ? p2 : FLTMAX;
        key[s] = ((unsigned long long)f2o(kv) << 32) | (unsigned)s;
    }
    bitonic512(key, tid);

    for (int i = tid; i < 512; i += 256) {
        int s = (int)(key[i] & 0xffffffffu);
        float p = oph[s], m = mg[s];
        size_t row = ((size_t)b * 512 + i) * 33;
        float base = 6.2831855f * p;
#pragma unroll
        for (int h = 0; h < 16; ++h) {
            float sv, cv;
            sincosf(base * (float)(h + 1), &sv, &cv);
            g_emb[row + h]      = cv;
            g_emb[row + 16 + h] = sv;
        }
        g_emb[row + 32] = m;
        g_valid[b * 512 + i] = (float)oval[s];
    }
}

// ---------------- 2a. scalar GEMM (K=33): C = A.B^T + bias ----------------
__global__ void __launch_bounds__(256) gemm_tn(const float* __restrict__ A,
                                               const float* __restrict__ B,
                                               const float* __restrict__ bias,
                                               float* __restrict__ C,
                                               int M, int N, int K) {
    __shared__ float As[8][132], Bs[8][132];
    int bm = blockIdx.y * 128, bn = blockIdx.x * 128;
    int tid = threadIdx.x, tm = tid >> 4, tn = tid & 15;
    float acc[8][8];
#pragma unroll
    for (int i = 0; i < 8; ++i)
#pragma unroll
        for (int j = 0; j < 8; ++j) acc[i][j] = 0.f;

    for (int k0 = 0; k0 < K; k0 += 8) {
#pragma unroll
        for (int i = 0; i < 4; ++i) {
            int idx = tid + i * 256;
            int r = idx >> 3, kk = idx & 7;
            As[kk][r] = (k0 + kk < K) ? A[(size_t)(bm + r) * K + k0 + kk] : 0.f;
            Bs[kk][r] = (k0 + kk < K) ? B[(size_t)(bn + r) * K + k0 + kk] : 0.f;
        }
        __syncthreads();
#pragma unroll
        for (int kk = 0; kk < 8; ++kk) {
            float a[8], bb[8];
#pragma unroll
            for (int i = 0; i < 8; ++i) a[i]  = As[kk][tm * 8 + i];
#pragma unroll
            for (int j = 0; j < 8; ++j) bb[j] = Bs[kk][tn * 8 + j];
#pragma unroll
            for (int i = 0; i < 8; ++i)
#pragma unroll
                for (int j = 0; j < 8; ++j) acc[i][j] += a[i] * bb[j];
        }
        __syncthreads();
    }
#pragma unroll
    for (int i = 0; i < 8; ++i)
#pragma unroll
        for (int j = 0; j < 8; ++j)
            C[(size_t)(bm + tm * 8 + i) * N + bn + tn * 8 + j] = acc[i][j] + bias[bn + tn * 8 + j];
}

// ---------------- 2b. packed-f32x2 GEMM (K multiple of 8) ----------------
__global__ void __launch_bounds__(256) gemm_tn_x2(const float* __restrict__ A,
                                                  const float* __restrict__ B,
                                                  const float* __restrict__ bias,
                                                  float* __restrict__ C,
                                                  int M, int N, int K) {
    __shared__ float As[8][132], Bs[8][132];
    int bm = blockIdx.y * 128, bn = blockIdx.x * 128;
    int tid = threadIdx.x, tm = tid >> 4, tn = tid & 15;
    unsigned long long acc[8][4];
#pragma unroll
    for (int i = 0; i < 8; ++i)
#pragma unroll
        for (int j = 0; j < 4; ++j) acc[i][j] = 0ull;

    for (int k0 = 0; k0 < K; k0 += 8) {
#pragma unroll
        for (int i = 0; i < 4; ++i) {
            int idx = tid + i * 256;
            int r = idx >> 3, kk = idx & 7;
            As[kk][r] = A[(size_t)(bm + r) * K + k0 + kk];
            Bs[kk][r] = B[(size_t)(bn + r) * K + k0 + kk];
        }
        __syncthreads();
#pragma unroll
        for (int kk = 0; kk < 8; ++kk) {
            float4 alo = *(const float4*)&As[kk][tm * 8];
            float4 ahi = *(const float4*)&As[kk][tm * 8 + 4];
            unsigned long long a2[8];
            PACK2(a2[0], alo.x); PACK2(a2[1], alo.y); PACK2(a2[2], alo.z); PACK2(a2[3], alo.w);
            PACK2(a2[4], ahi.x); PACK2(a2[5], ahi.y); PACK2(a2[6], ahi.z); PACK2(a2[7], ahi.w);
            unsigned long long b2[4];
#pragma unroll
            for (int jj = 0; jj < 4; ++jj)
                b2[jj] = *(const unsigned long long*)&Bs[kk][tn * 8 + jj * 2];
#pragma unroll
            for (int i = 0; i < 8; ++i)
#pragma unroll
                for (int jj = 0; jj < 4; ++jj)
                    FMA2(acc[i][jj], a2[i], b2[jj]);
        }
        __syncthreads();
    }
#pragma unroll
    for (int i = 0; i < 8; ++i) {
        size_t row = (size_t)(bm + tm * 8 + i);
#pragma unroll
        for (int jj = 0; jj < 4; ++jj) {
            int col = bn + tn * 8 + jj * 2;
            float lo, hi;
            UNPACK2(lo, hi, acc[i][jj]);
            float2 v = make_float2(lo + bias[col], hi + bias[col + 1]);
            *(float2*)&C[row * N + col] = v;
        }
    }
}

// ---------------- 3. persistent GRU layer (champion; padded barrier lines) ----------------
// grid = 128: group g = blockIdx/32 owns batches [16g,16g+16); chunk c = blockIdx%32 owns h-cols [16c,16c+16)
// smem layout (bytes): W 48x516 f32 (99072) | h 8 pair-rows x 514 float2 (32896) | partials 384x17 ull (52224) | bhh 48 f32
#define GRU_SMEM_BYTES (48*516*4 + 8*514*8 + 384*17*8 + 48*4)
__global__ void __launch_bounds__(256, 1) gru_kernel(const float* __restrict__ xw,
                                                     const float* __restrict__ whh,
                                                     const float* __restrict__ bhh,
                                                     float* __restrict__ hout,
                                                     int* __restrict__ bar) {
    int c = blockIdx.x & 31;
    int grp = blockIdx.x >> 5;
    int b0 = grp * 16;
    int tid = threadIdx.x;

    extern __shared__ float sm[];
    float*  sW   = sm;                                   // 48 x 516
    float2* sh2  = (float2*)(sm + 48 * 516);             // 8 pair-rows x 514 (k-major, (b,b+1) packed)
    unsigned long long* spu = (unsigned long long*)(sh2 + 8 * 514);  // 384 x 17
    float*  sbhh = (float*)(spu + 384 * 17);             // 48

    // load W_hh slice: smem row r = g*16+j <- global row g*512 + c*16 + j
    for (int idx = tid; idx < 48 * 512; idx += 256) {
        int r = idx >> 9, k = idx & 511;
        int grow = (r >> 4) * 512 + c * 16 + (r & 15);
        sW[r * 516 + k] = whh[(size_t)grow * 512 + k];
    }
    if (tid < 48) sbhh[tid] = bhh[(tid >> 4) * 512 + c * 16 + (tid & 15)];
    for (int idx = tid; idx < 8 * 514; idx += 256) sh2[idx] = make_float2(0.f, 0.f);  // h0 = 0
    __syncthreads();

    // dot-phase mapping: lane = jig(0..7) | bq(1b) | kh(1b); ks = warp*2+kh (0..15), kchunk=32
    int jig = tid & 7;
    int bq  = (tid >> 3) & 1;
    int kh  = (tid >> 4) & 1;
    int ks  = ((tid >> 5) << 1) | kh;

    const float* Wp[6];
#pragma unroll
    for (int g = 0; g < 3; ++g)
#pragma unroll
        for (int hf = 0; hf < 2; ++hf)
            Wp[g * 2 + hf] = sW + (g * 16 + jig + hf * 8) * 516 + ks * 32;
    const float2* hp[4];
#pragma unroll
    for (int pr = 0; pr < 4; ++pr) hp[pr] = sh2 + (bq * 4 + pr) * 514 + ks * 32;

    // combine mapping (tid < 128): column cj within chunk, batch pair pp
    int cj = tid & 15, pp = tid >> 4;
    const float* xbase = xw + ((size_t)(b0 + 2 * pp) * 512) * 1536 + c * 16 + cj;

    // padded barrier: this group's counter on its own 128B line
    int* mybar = bar + grp * 32;

    int target = 0;
    for (int t = 0; t < 512; ++t) {
        // prefetch xW for combine (consumed ~3000 cycles later)
        float xr0 = 0.f, xz0 = 0.f, xn0 = 0.f, xr1 = 0.f, xz1 = 0.f, xn1 = 0.f;
        if (tid < 128) {
            const float* x0 = xbase + (size_t)t * 1536;
            const float* x1 = x0 + (size_t)512 * 1536;
            xr0 = x0[0]; xz0 = x0[512]; xn0 = x0[1024];
            xr1 = x1[0]; xz1 = x1[512]; xn1 = x1[1024];
        }

        unsigned long long acc[6][4];
#pragma unroll
        for (int a = 0; a < 6; ++a)
#pragma unroll
            for (int p = 0; p < 4; ++p) acc[a][p] = 0ull;

#pragma unroll
        for (int i = 0; i < 8; ++i) {
            unsigned long long wq[6][4];
#pragma unroll
            for (int a = 0; a < 6; ++a) {
                float4 w = *(const float4*)(Wp[a] + i * 4);
                PACK2(wq[a][0], w.x); PACK2(wq[a][1], w.y);
                PACK2(wq[a][2], w.z); PACK2(wq[a][3], w.w);
            }
#pragma unroll
            for (int p = 0; p < 4; ++p) {
                ulonglong2 h01 = *(const ulonglong2*)(hp[p] + i * 4);
                ulonglong2 h23 = *(const ulonglong2*)(hp[p] + i * 4 + 2);
#pragma unroll
                for (int a = 0; a < 6; ++a) {
                    FMA2(acc[a][p], wq[a][0], h01.x);
                    FMA2(acc[a][p], wq[a][1], h01.y);
                    FMA2(acc[a][p], wq[a][2], h23.x);
                    FMA2(acc[a][p], wq[a][3], h23.y);
                }
            }
        }

        // write partials: spu[((pair*16+col)*3+g)*17 + ks]
#pragma unroll
        for (int a = 0; a < 6; ++a) {
            int g = a >> 1, col = jig + (a & 1) * 8;
#pragma unroll
            for (int p = 0; p < 4; ++p) {
                int pg = bq * 4 + p;
                spu[((pg * 16 + col) * 3 + g) * 17 + ks] = acc[a][p];
            }
        }
        __syncthreads();

        // combine + activation (128 threads: 16 cols x 8 pairs)
        if (tid < 128) {
            float s[3][2];
#pragma unroll
            for (int g = 0; g < 3; ++g) {
                float sx = 0.f, sy = 0.f;
                int base = ((pp * 16 + cj) * 3 + g) * 17;
#pragma unroll
                for (int q = 0; q < 16; ++q) {
                    float lo, hi;
                    UNPACK2(lo, hi, spu[base + q]);
                    sx += lo; sy += hi;
                }
                s[g][0] = sx; s[g][1] = sy;
            }
            float2 hprev = sh2[pp * 514 + c * 16 + cj];
            float br = sbhh[cj], bz = sbhh[16 + cj], bnn = sbhh[32 + cj];

            float r0 = 1.f / (1.f + expf(-(xr0 + s[0][0] + br)));
            float z0 = 1.f / (1.f + expf(-(xz0 + s[1][0] + bz)));
            float n0 = tanhf(xn0 + r0 * (s[2][0] + bnn));
            float h0 = (1.f - z0) * n0 + z0 * hprev.x;

            float r1 = 1.f / (1.f + expf(-(xr1 + s[0][1] + br)));
            float z1 = 1.f / (1.f + expf(-(xz1 + s[1][1] + bz)));
            float n1 = tanhf(xn1 + r1 * (s[2][1] + bnn));
            float h1v = (1.f - z1) * n1 + z1 * hprev.y;

            size_t o0 = ((size_t)(b0 + 2 * pp) * 512 + t) * 512 + c * 16 + cj;
            hout[o0]             = h0;
            hout[o0 + 512 * 512] = h1v;
        }
        __syncthreads();

        // group barrier (monotonic counter on a private 128B line)
        if (tid == 0) {
            __threadfence();
            atomicAdd(mybar, 1);
            target += 32;
            volatile int* vb = (volatile int*)mybar;
            while (*vb < target) __nanosleep(32);
        }
        __syncthreads();

        // reload full h_t into pair layout (addresses fresh each t -> no L1 staleness)
#pragma unroll
        for (int it = 0; it < 4; ++it) {
            int idx = tid + it * 256;
            int p = idx >> 7, kq = idx & 127;
            size_t gg = ((size_t)(b0 + 2 * p) * 512 + t) * 512 + kq * 4;
            float4 va = *(const float4*)&hout[gg];
            float4 vb2 = *(const float4*)&hout[gg + 512 * 512];
            float2* dst = sh2 + p * 514 + kq * 4;
            *(float4*)(dst)     = make_float4(va.x, vb2.x, va.y, vb2.y);
            *(float4*)(dst + 2) = make_float4(va.z, vb2.z, va.w, vb2.w);
        }
        __syncthreads();
    }
}

// ---------------- 4. masked mean + MLP head ----------------
__global__ void __launch_bounds__(256) final_kernel(const float* __restrict__ Wl1,
                                                    const float* __restrict__ bl1,
                                                    const float* __restrict__ Wl2,
                                                    const float* __restrict__ bl2,
                                                    float* __restrict__ out) {
    int b = blockIdx.x, tid = threadIdx.x;
    __shared__ float sval[512], ctx[512], h1[512], red[8];
    __shared__ float s_cnt;
    int warp = tid >> 5, lane = tid & 31;

    for (int s = tid; s < 512; s += 256) sval[s] = g_valid[b * 512 + s];
    __syncthreads();

    float cp = sval[tid] + sval[tid + 256];
#pragma unroll
    for (int o = 16; o > 0; o >>= 1) cp += __shfl_down_sync(0xffffffffu, cp, o);
    if (lane == 0) red[warp] = cp;
    __syncthreads();
    if (tid == 0) {
        float cnt = 0.f;
        for (int w = 0; w < 8; ++w) cnt += red[w];
        s_cnt = cnt;
    }
    __syncthreads();

#pragma unroll
    for (int cc = 0; cc < 2; ++cc) {
        int col = tid + cc * 256;
        float acc = 0.f;
        for (int t = 0; t < 512; ++t)
            acc += g_h[((size_t)b * 512 + t) * 512 + col] * sval[t];
        ctx[col] = acc / s_cnt;
    }
    __syncthreads();

#pragma unroll
    for (int cc = 0; cc < 2; ++cc) {
        int o = tid + cc * 256;
        float a = 0.f;
        const float* wr = Wl1 + (size_t)o * 512;
        for (int k = 0; k < 512; ++k) a += ctx[k] * wr[k];
        a += bl1[o];
        h1[o] = 0.5f * a * (1.0f + erff(a * 0.70710678118654752f));
    }
    __syncthreads();

    for (int o = warp; o < 16; o += 8) {
        float a = 0.f;
        const float* wr = Wl2 + (size_t)o * 512;
        for (int k = lane; k < 512; k += 32) a += h1[k] * wr[k];
#pragma unroll
        for (int s = 16; s > 0; s >>= 1) a += __shfl_down_sync(0xffffffffu, a, s);
        if (lane == 0) out[b * 16 + o] = a + bl2[o];
    }
}

// ---------------- launch ----------------
extern "C" void kernel_launch(void* const* d_in, const int* in_sizes, int n_in,
                              void* d_out, int out_size) {
    const float* lc    = (const float*)d_in[0];
    const float* freq  = (const float*)d_in[2];
    const float* W_ih0 = (const float*)d_in[3];
    const float* b_ih0 = (const float*)d_in[4];
    const float* W_hh0 = (const float*)d_in[5];
    const float* b_hh0 = (const float*)d_in[6];
    const float* W_ih1 = (const float*)d_in[7];
    const float* b_ih1 = (const float*)d_in[8];
    const float* W_hh1 = (const float*)d_in[9];
    const float* b_hh1 = (const float*)d_in[10];
    const float* Wl1   = (const float*)d_in[11];
    const float* bl1   = (const float*)d_in[12];
    const float* Wl2   = (const float*)d_in[13];
    const float* bl2   = (const float*)d_in[14];
    float* out = (float*)d_out;

    float *p_emb, *p_xw, *p_h;
    int* p_bar;
    cudaGetSymbolAddress((void**)&p_emb, g_emb);
    cudaGetSymbolAddress((void**)&p_xw,  g_xw);
    cudaGetSymbolAddress((void**)&p_h,   g_h);
    cudaGetSymbolAddress((void**)&p_bar, g_bar);

    cudaFuncSetAttribute(gru_kernel, cudaFuncAttributeMaxDynamicSharedMemorySize, GRU_SMEM_BYTES);

    zero_bar_kernel<<<1, 256>>>();
    prep_kernel<<<64, 256>>>(lc, freq);

    // xW0 = emb @ W_ih0^T + b_ih0   (M=32768, N=1536, K=33) — scalar (K odd)
    gemm_tn<<<dim3(12, 256), 256>>>(p_emb, W_ih0, b_ih0, p_xw, 32768, 1536, 33);

    // GRU layer 0
    gru_kernel<<<128, 256, GRU_SMEM_BYTES>>>(p_xw, W_hh0, b_hh0, p_h, p_bar);

    // xW1 = hs0 @ W_ih1^T + b_ih1   (K=512) — packed f32x2
    gemm_tn_x2<<<dim3(12, 256), 256>>>(p_h, W_ih1, b_ih1, p_xw, 32768, 1536, 512);

    // GRU layer 1 (separate barrier counters on their own lines; hs1 overwrites g_h)
    gru_kernel<<<128, 256, GRU_SMEM_BYTES>>>(p_xw, W_hh1, b_hh1, p_h, p_bar + 4 * 32);

    final_kernel<<<64, 256>>>(Wl1, bl1, Wl2, bl2, out);
}

// round 17
// speedup vs baseline: 1.0624x; 1.0044x over previous
#include <cuda_runtime.h>
#include <math.h>
#include <stdint.h>

#define FLTMAX 3.402823466e38f

// ---------------- static device scratch ----------------
__device__ float g_emb[(size_t)32768 * 33];     // [b*512+s][33]
__device__ float g_xw [(size_t)32768 * 1536];   // [b*512+t][1536]
__device__ float g_h  [(size_t)32768 * 512];    // [b*512+t][512]
__device__ float g_valid[32768];                // final-order validity (0/1)
// one barrier counter per 128-byte L2 line: group g of layer l at index (l*4+g)*32
__device__ int   g_bar[8 * 32];

// ---------------- f32x2 packed math (sm_100+) ----------------
#define PACK2(d, s)  asm("mov.b64 %0, {%1, %1};" : "=l"(d) : "r"(__float_as_uint(s)))
#define UNPACK2(lo, hi, v) asm("mov.b64 {%0, %1}, %2;" : "=f"(lo), "=f"(hi) : "l"(v))
#define FMA2(a, x, y) asm("fma.rn.f32x2 %0, %1, %2, %0;" : "+l"(a) : "l"(x), "l"(y))

// ---------------- streaming (L2-only) global access ----------------
__device__ __forceinline__ float ldcg_f(const float* p) {
    float v;
    asm volatile("ld.global.cg.f32 %0, [%1];" : "=f"(v) : "l"(p));
    return v;
}
__device__ __forceinline__ float4 ldcg_f4(const float* p) {
    float4 v;
    asm volatile("ld.global.cg.v4.f32 {%0,%1,%2,%3}, [%4];"
                 : "=f"(v.x), "=f"(v.y), "=f"(v.z), "=f"(v.w) : "l"(p));
    return v;
}
__device__ __forceinline__ void stcg_f(float* p, float v) {
    asm volatile("st.global.cg.f32 [%0], %1;" :: "l"(p), "f"(v));
}

// ---------------- helpers ----------------
__device__ __forceinline__ unsigned f2o(float x) {
    unsigned u = __float_as_uint(x);
    return (u & 0x80000000u) ? ~u : (u | 0x80000000u);
}

// 512-element ascending bitonic sort, 256 threads, 64-bit keys in smem
__device__ void bitonic512(unsigned long long* key, int tid) {
    for (int k = 2; k <= 512; k <<= 1) {
        for (int j = k >> 1; j > 0; j >>= 1) {
            __syncthreads();
            int low = tid & (j - 1);
            int i   = ((tid & ~(j - 1)) << 1) | low;
            int i2  = i | j;
            bool up = ((i & k) == 0);
            unsigned long long a = key[i], c = key[i2];
            if ((a > c) == up) { key[i] = c; key[i2] = a; }
        }
    }
    __syncthreads();
}

__global__ void zero_bar_kernel() {
    if (threadIdx.x < 8 * 32) g_bar[threadIdx.x] = 0;
}

// ---------------- 1. preprocess (verified: rel_err 5.9e-7) ----------------
__global__ void __launch_bounds__(256) prep_kernel(const float* __restrict__ lc,
                                                   const float* __restrict__ freq) {
    int b = blockIdx.x, tid = threadIdx.x;
    __shared__ float ph[512], mg[512], sps[512], sms[512], oph[512];
    __shared__ int   oval[512];
    __shared__ unsigned long long key[512];
    __shared__ float smoothv[52];
    __shared__ float s_shift;

    float period = 2.0f / freq[b];
    for (int s = tid; s < 512; s += 256) {
        float tm = lc[b * 1536 + s];
        float m  = lc[b * 1536 + 512 + s];
        float p  = fmodf(tm, period) / period;
        ph[s] = p; mg[s] = m;
        key[s] = ((unsigned long long)f2o(p) << 32) | (unsigned)s;
    }
    bitonic512(key, tid);

    for (int i = tid; i < 512; i += 256) {
        int p = (int)(key[i] & 0xffffffffu);
        sps[i] = ph[p]; sms[i] = mg[p];
    }
    __syncthreads();

    for (int i = tid; i < 512; i += 256) {
        float p0 = sps[i];
        const int offs[4] = {-2, -1, 1, 2};
        float wv[4], mv[4];
        float wsum = 0.f, wm = 0.f;
#pragma unroll
        for (int d = 0; d < 4; ++d) {
            int j = (i + offs[d] + 512) & 511;
            float dp = sps[j] - p0 - 0.5f;
            dp = dp - floorf(dp) - 0.5f;
            float w = 0.75f * (1.0f - dp * dp);
            wv[d] = w; mv[d] = sms[j];
            wsum += w; wm += w * mv[d];
        }
        float loc = wm / wsum;
        float var = 0.f;
#pragma unroll
        for (int d = 0; d < 4; ++d) { float e = mv[d] - loc; var += e * e * wv[d]; }
        float scale = sqrtf(var / (wsum - 1.0f));
        float thr = loc + 5.0f * scale;
        int valid = !(sms[i] > thr);
        int p = (int)(key[i] & 0xffffffffu);
        oval[p] = valid;
    }
    __syncthreads();

    int warp = tid >> 5, lane = tid & 31;
    for (int g = warp; g < 50; g += 8) {
        float gv = (float)g * (1.0f / 49.0f);
        float num = 0.f, den = 0.f;
        for (int s = lane; s < 512; s += 32) {
            if (oval[s]) {
                float d = gv - ph[s];
                float K = expf((cosf(6.2831855f * d) - 1.0f) / 0.01f);
                num += K * mg[s]; den += K;
            }
        }
#pragma unroll
        for (int o = 16; o > 0; o >>= 1) {
            num += __shfl_down_sync(0xffffffffu, num, o);
            den += __shfl_down_sync(0xffffffffu, den, o);
        }
        if (lane == 0) smoothv[g] = num / den;
    }
    __syncthreads();
    if (tid == 0) {
        float best = smoothv[0]; int bi = 0;
        for (int g = 1; g < 50; ++g)
            if (smoothv[g] > best) { best = smoothv[g]; bi = g; }
        s_shift = (float)bi * (1.0f / 49.0f);
    }
    __syncthreads();

    float shift = s_shift;
    for (int s = tid; s < 512; s += 256) {
        float p2 = ph[s] - shift;
        oph[s] = p2;
        float kv = oval[s] ? p2 : FLTMAX;
        key[s] = ((unsigned long long)f2o(kv) << 32) | (unsigned)s;
    }
    bitonic512(key, tid);

    for (int i = tid; i < 512; i += 256) {
        int s = (int)(key[i] & 0xffffffffu);
        float p = oph[s], m = mg[s];
        size_t row = ((size_t)b * 512 + i) * 33;
        float base = 6.2831855f * p;
#pragma unroll
        for (int h = 0; h < 16; ++h) {
            float sv, cv;
            sincosf(base * (float)(h + 1), &sv, &cv);
            g_emb[row + h]      = cv;
            g_emb[row + 16 + h] = sv;
        }
        g_emb[row + 32] = m;
        g_valid[b * 512 + i] = (float)oval[s];
    }
}

// ---------------- 2a. scalar GEMM (K=33): C = A.B^T + bias ----------------
__global__ void __launch_bounds__(256) gemm_tn(const float* __restrict__ A,
                                               const float* __restrict__ B,
                                               const float* __restrict__ bias,
                                               float* __restrict__ C,
                                               int M, int N, int K) {
    __shared__ float As[8][132], Bs[8][132];
    int bm = blockIdx.y * 128, bn = blockIdx.x * 128;
    int tid = threadIdx.x, tm = tid >> 4, tn = tid & 15;
    float acc[8][8];
#pragma unroll
    for (int i = 0; i < 8; ++i)
#pragma unroll
        for (int j = 0; j < 8; ++j) acc[i][j] = 0.f;

    for (int k0 = 0; k0 < K; k0 += 8) {
#pragma unroll
        for (int i = 0; i < 4; ++i) {
            int idx = tid + i * 256;
            int r = idx >> 3, kk = idx & 7;
            As[kk][r] = (k0 + kk < K) ? A[(size_t)(bm + r) * K + k0 + kk] : 0.f;
            Bs[kk][r] = (k0 + kk < K) ? B[(size_t)(bn + r) * K + k0 + kk] : 0.f;
        }
        __syncthreads();
#pragma unroll
        for (int kk = 0; kk < 8; ++kk) {
            float a[8], bb[8];
#pragma unroll
            for (int i = 0; i < 8; ++i) a[i]  = As[kk][tm * 8 + i];
#pragma unroll
            for (int j = 0; j < 8; ++j) bb[j] = Bs[kk][tn * 8 + j];
#pragma unroll
            for (int i = 0; i < 8; ++i)
#pragma unroll
                for (int j = 0; j < 8; ++j) acc[i][j] += a[i] * bb[j];
        }
        __syncthreads();
    }
#pragma unroll
    for (int i = 0; i < 8; ++i)
#pragma unroll
        for (int j = 0; j < 8; ++j)
            C[(size_t)(bm + tm * 8 + i) * N + bn + tn * 8 + j] = acc[i][j] + bias[bn + tn * 8 + j];
}

// ---------------- 2b. packed-f32x2 GEMM (K multiple of 8) ----------------
__global__ void __launch_bounds__(256) gemm_tn_x2(const float* __restrict__ A,
                                                  const float* __restrict__ B,
                                                  const float* __restrict__ bias,
                                                  float* __restrict__ C,
                                                  int M, int N, int K) {
    __shared__ float As[8][132], Bs[8][132];
    int bm = blockIdx.y * 128, bn = blockIdx.x * 128;
    int tid = threadIdx.x, tm = tid >> 4, tn = tid & 15;
    unsigned long long acc[8][4];
#pragma unroll
    for (int i = 0; i < 8; ++i)
#pragma unroll
        for (int j = 0; j < 4; ++j) acc[i][j] = 0ull;

    for (int k0 = 0; k0 < K; k0 += 8) {
#pragma unroll
        for (int i = 0; i < 4; ++i) {
            int idx = tid + i * 256;
            int r = idx >> 3, kk = idx & 7;
            As[kk][r] = A[(size_t)(bm + r) * K + k0 + kk];
            Bs[kk][r] = B[(size_t)(bn + r) * K + k0 + kk];
        }
        __syncthreads();
#pragma unroll
        for (int kk = 0; kk < 8; ++kk) {
            float4 alo = *(const float4*)&As[kk][tm * 8];
            float4 ahi = *(const float4*)&As[kk][tm * 8 + 4];
            unsigned long long a2[8];
            PACK2(a2[0], alo.x); PACK2(a2[1], alo.y); PACK2(a2[2], alo.z); PACK2(a2[3], alo.w);
            PACK2(a2[4], ahi.x); PACK2(a2[5], ahi.y); PACK2(a2[6], ahi.z); PACK2(a2[7], ahi.w);
            unsigned long long b2[4];
#pragma unroll
            for (int jj = 0; jj < 4; ++jj)
                b2[jj] = *(const unsigned long long*)&Bs[kk][tn * 8 + jj * 2];
#pragma unroll
            for (int i = 0; i < 8; ++i)
#pragma unroll
                for (int jj = 0; jj < 4; ++jj)
                    FMA2(acc[i][jj], a2[i], b2[jj]);
        }
        __syncthreads();
    }
#pragma unroll
    for (int i = 0; i < 8; ++i) {
        size_t row = (size_t)(bm + tm * 8 + i);
#pragma unroll
        for (int jj = 0; jj < 4; ++jj) {
            int col = bn + tn * 8 + jj * 2;
            float lo, hi;
            UNPACK2(lo, hi, acc[i][jj]);
            float2 v = make_float2(lo + bias[col], hi + bias[col + 1]);
            *(float2*)&C[row * N + col] = v;
        }
    }
}

// ---------------- 3. persistent GRU layer (champion; padded barriers; .cg streaming) ----------------
// grid = 128: group g = blockIdx/32 owns batches [16g,16g+16); chunk c = blockIdx%32 owns h-cols [16c,16c+16)
// smem layout (bytes): W 48x516 f32 (99072) | h 8 pair-rows x 514 float2 (32896) | partials 384x17 ull (52224) | bhh 48 f32
#define GRU_SMEM_BYTES (48*516*4 + 8*514*8 + 384*17*8 + 48*4)
__global__ void __launch_bounds__(256, 1) gru_kernel(const float* __restrict__ xw,
                                                     const float* __restrict__ whh,
                                                     const float* __restrict__ bhh,
                                                     float* __restrict__ hout,
                                                     int* __restrict__ bar) {
    int c = blockIdx.x & 31;
    int grp = blockIdx.x >> 5;
    int b0 = grp * 16;
    int tid = threadIdx.x;

    extern __shared__ float sm[];
    float*  sW   = sm;                                   // 48 x 516
    float2* sh2  = (float2*)(sm + 48 * 516);             // 8 pair-rows x 514 (k-major, (b,b+1) packed)
    unsigned long long* spu = (unsigned long long*)(sh2 + 8 * 514);  // 384 x 17
    float*  sbhh = (float*)(spu + 384 * 17);             // 48

    // load W_hh slice: smem row r = g*16+j <- global row g*512 + c*16 + j
    for (int idx = tid; idx < 48 * 512; idx += 256) {
        int r = idx >> 9, k = idx & 511;
        int grow = (r >> 4) * 512 + c * 16 + (r & 15);
        sW[r * 516 + k] = whh[(size_t)grow * 512 + k];
    }
    if (tid < 48) sbhh[tid] = bhh[(tid >> 4) * 512 + c * 16 + (tid & 15)];
    for (int idx = tid; idx < 8 * 514; idx += 256) sh2[idx] = make_float2(0.f, 0.f);  // h0 = 0
    __syncthreads();

    // dot-phase mapping: lane = jig(0..7) | bq(1b) | kh(1b); ks = warp*2+kh (0..15), kchunk=32
    int jig = tid & 7;
    int bq  = (tid >> 3) & 1;
    int kh  = (tid >> 4) & 1;
    int ks  = ((tid >> 5) << 1) | kh;

    const float* Wp[6];
#pragma unroll
    for (int g = 0; g < 3; ++g)
#pragma unroll
        for (int hf = 0; hf < 2; ++hf)
            Wp[g * 2 + hf] = sW + (g * 16 + jig + hf * 8) * 516 + ks * 32;
    const float2* hp[4];
#pragma unroll
    for (int pr = 0; pr < 4; ++pr) hp[pr] = sh2 + (bq * 4 + pr) * 514 + ks * 32;

    // combine mapping (tid < 128): column cj within chunk, batch pair pp
    int cj = tid & 15, pp = tid >> 4;
    const float* xbase = xw + ((size_t)(b0 + 2 * pp) * 512) * 1536 + c * 16 + cj;

    // padded barrier: this group's counter on its own 128B line
    int* mybar = bar + grp * 32;

    int target = 0;
    for (int t = 0; t < 512; ++t) {
        // prefetch xW for combine (consumed ~3000 cycles later); streaming L2-only
        float xr0 = 0.f, xz0 = 0.f, xn0 = 0.f, xr1 = 0.f, xz1 = 0.f, xn1 = 0.f;
        if (tid < 128) {
            const float* x0 = xbase + (size_t)t * 1536;
            const float* x1 = x0 + (size_t)512 * 1536;
            xr0 = ldcg_f(x0);        xz0 = ldcg_f(x0 + 512);  xn0 = ldcg_f(x0 + 1024);
            xr1 = ldcg_f(x1);        xz1 = ldcg_f(x1 + 512);  xn1 = ldcg_f(x1 + 1024);
        }

        unsigned long long acc[6][4];
#pragma unroll
        for (int a = 0; a < 6; ++a)
#pragma unroll
            for (int p = 0; p < 4; ++p) acc[a][p] = 0ull;

#pragma unroll
        for (int i = 0; i < 8; ++i) {
            unsigned long long wq[6][4];
#pragma unroll
            for (int a = 0; a < 6; ++a) {
                float4 w = *(const float4*)(Wp[a] + i * 4);
                PACK2(wq[a][0], w.x); PACK2(wq[a][1], w.y);
                PACK2(wq[a][2], w.z); PACK2(wq[a][3], w.w);
            }
#pragma unroll
            for (int p = 0; p < 4; ++p) {
                ulonglong2 h01 = *(const ulonglong2*)(hp[p] + i * 4);
                ulonglong2 h23 = *(const ulonglong2*)(hp[p] + i * 4 + 2);
#pragma unroll
                for (int a = 0; a < 6; ++a) {
                    FMA2(acc[a][p], wq[a][0], h01.x);
                    FMA2(acc[a][p], wq[a][1], h01.y);
                    FMA2(acc[a][p], wq[a][2], h23.x);
                    FMA2(acc[a][p], wq[a][3], h23.y);
                }
            }
        }

        // write partials: spu[((pair*16+col)*3+g)*17 + ks]
#pragma unroll
        for (int a = 0; a < 6; ++a) {
            int g = a >> 1, col = jig + (a & 1) * 8;
#pragma unroll
            for (int p = 0; p < 4; ++p) {
                int pg = bq * 4 + p;
                spu[((pg * 16 + col) * 3 + g) * 17 + ks] = acc[a][p];
            }
        }
        __syncthreads();

        // combine + activation (128 threads: 16 cols x 8 pairs)
        if (tid < 128) {
            float s[3][2];
#pragma unroll
            for (int g = 0; g < 3; ++g) {
                float sx = 0.f, sy = 0.f;
                int base = ((pp * 16 + cj) * 3 + g) * 17;
#pragma unroll
                for (int q = 0; q < 16; ++q) {
                    float lo, hi;
                    UNPACK2(lo, hi, spu[base + q]);
                    sx += lo; sy += hi;
                }
                s[g][0] = sx; s[g][1] = sy;
            }
            float2 hprev = sh2[pp * 514 + c * 16 + cj];
            float br = sbhh[cj], bz = sbhh[16 + cj], bnn = sbhh[32 + cj];

            float r0 = 1.f / (1.f + expf(-(xr0 + s[0][0] + br)));
            float z0 = 1.f / (1.f + expf(-(xz0 + s[1][0] + bz)));
            float n0 = tanhf(xn0 + r0 * (s[2][0] + bnn));
            float h0 = (1.f - z0) * n0 + z0 * hprev.x;

            float r1 = 1.f / (1.f + expf(-(xr1 + s[0][1] + br)));
            float z1 = 1.f / (1.f + expf(-(xz1 + s[1][1] + bz)));
            float n1 = tanhf(xn1 + r1 * (s[2][1] + bnn));
            float h1v = (1.f - z1) * n1 + z1 * hprev.y;

            size_t o0 = ((size_t)(b0 + 2 * pp) * 512 + t) * 512 + c * 16 + cj;
            stcg_f(&hout[o0], h0);
            stcg_f(&hout[o0 + 512 * 512], h1v);
        }
        __syncthreads();

        // group barrier (monotonic counter on a private 128B line)
        if (tid == 0) {
            __threadfence();
            atomicAdd(mybar, 1);
            target += 32;
            volatile int* vb = (volatile int*)mybar;
            while (*vb < target) __nanosleep(32);
        }
        __syncthreads();

        // reload full h_t into pair layout; L2-only loads (structurally immune to L1 staleness)
#pragma unroll
        for (int it = 0; it < 4; ++it) {
            int idx = tid + it * 256;
            int p = idx >> 7, kq = idx & 127;
            size_t gg = ((size_t)(b0 + 2 * p) * 512 + t) * 512 + kq * 4;
            float4 va  = ldcg_f4(&hout[gg]);
            float4 vb2 = ldcg_f4(&hout[gg + 512 * 512]);
            float2* dst = sh2 + p * 514 + kq * 4;
            *(float4*)(dst)     = make_float4(va.x, vb2.x, va.y, vb2.y);
            *(float4*)(dst + 2) = make_float4(va.z, vb2.z, va.w, vb2.w);
        }
        __syncthreads();
    }
}

// ---------------- 4. masked mean + MLP head ----------------
__global__ void __launch_bounds__(256) final_kernel(const float* __restrict__ Wl1,
                                                    const float* __restrict__ bl1,
                                                    const float* __restrict__ Wl2,
                                                    const float* __restrict__ bl2,
                                                    float* __restrict__ out) {
    int b = blockIdx.x, tid = threadIdx.x;
    __shared__ float sval[512], ctx[512], h1[512], red[8];
    __shared__ float s_cnt;
    int warp = tid >> 5, lane = tid & 31;

    for (int s = tid; s < 512; s += 256) sval[s] = g_valid[b * 512 + s];
    __syncthreads();

    float cp = sval[tid] + sval[tid + 256];
#pragma unroll
    for (int o = 16; o > 0; o >>= 1) cp += __shfl_down_sync(0xffffffffu, cp, o);
    if (lane == 0) red[warp] = cp;
    __syncthreads();
    if (tid == 0) {
        float cnt = 0.f;
        for (int w = 0; w < 8; ++w) cnt += red[w];
        s_cnt = cnt;
    }
    __syncthreads();

#pragma unroll
    for (int cc = 0; cc < 2; ++cc) {
        int col = tid + cc * 256;
        float acc = 0.f;
        for (int t = 0; t < 512; ++t)
            acc += g_h[((size_t)b * 512 + t) * 512 + col] * sval[t];
        ctx[col] = acc / s_cnt;
    }
    __syncthreads();

#pragma unroll
    for (int cc = 0; cc < 2; ++cc) {
        int o = tid + cc * 256;
        float a = 0.f;
        const float* wr = Wl1 + (size_t)o * 512;
        for (int k = 0; k < 512; ++k) a += ctx[k] * wr[k];
        a += bl1[o];
        h1[o] = 0.5f * a * (1.0f + erff(a * 0.70710678118654752f));
    }
    __syncthreads();

    for (int o = warp; o < 16; o += 8) {
        float a = 0.f;
        const float* wr = Wl2 + (size_t)o * 512;
        for (int k = lane; k < 512; k += 32) a += h1[k] * wr[k];
#pragma unroll
        for (int s = 16; s > 0; s >>= 1) a += __shfl_down_sync(0xffffffffu, a, s);
        if (lane == 0) out[b * 16 + o] = a + bl2[o];
    }
}

// ---------------- launch ----------------
extern "C" void kernel_launch(void* const* d_in, const int* in_sizes, int n_in,
                              void* d_out, int out_size) {
    const float* lc    = (const float*)d_in[0];
    const float* freq  = (const float*)d_in[2];
    const float* W_ih0 = (const float*)d_in[3];
    const float* b_ih0 = (const float*)d_in[4];
    const float* W_hh0 = (const float*)d_in[5];
    const float* b_hh0 = (const float*)d_in[6];
    const float* W_ih1 = (const float*)d_in[7];
    const float* b_ih1 = (const float*)d_in[8];
    const float* W_hh1 = (const float*)d_in[9];
    const float* b_hh1 = (const float*)d_in[10];
    const float* Wl1   = (const float*)d_in[11];
    const float* bl1   = (const float*)d_in[12];
    const float* Wl2   = (const float*)d_in[13];
    const float* bl2   = (const float*)d_in[14];
    float* out = (float*)d_out;

    float *p_emb, *p_xw, *p_h;
    int* p_bar;
    cudaGetSymbolAddress((void**)&p_emb, g_emb);
    cudaGetSymbolAddress((void**)&p_xw,  g_xw);
    cudaGetSymbolAddress((void**)&p_h,   g_h);
    cudaGetSymbolAddress((void**)&p_bar, g_bar);

    cudaFuncSetAttribute(gru_kernel, cudaFuncAttributeMaxDynamicSharedMemorySize, GRU_SMEM_BYTES);

    zero_bar_kernel<<<1, 256>>>();
    prep_kernel<<<64, 256>>>(lc, freq);

    // xW0 = emb @ W_ih0^T + b_ih0   (M=32768, N=1536, K=33) — scalar (K odd)
    gemm_tn<<<dim3(12, 256), 256>>>(p_emb, W_ih0, b_ih0, p_xw, 32768, 1536, 33);

    // GRU layer 0
    gru_kernel<<<128, 256, GRU_SMEM_BYTES>>>(p_xw, W_hh0, b_hh0, p_h, p_bar);

    // xW1 = hs0 @ W_ih1^T + b_ih1   (K=512) — packed f32x2
    gemm_tn_x2<<<dim3(12, 256), 256>>>(p_h, W_ih1, b_ih1, p_xw, 32768, 1536, 512);

    // GRU layer 1 (separate barrier counters on their own lines; hs1 overwrites g_h)
    gru_kernel<<<128, 256, GRU_SMEM_BYTES>>>(p_xw, W_hh1, b_hh1, p_h, p_bar + 4 * 32);

    final_kernel<<<64, 256>>>(Wl1, bl1, Wl2, bl2, out);
}